// round 16
// baseline (speedup 1.0000x reference)
#include <cuda_runtime.h>
#include <cuda_bf16.h>
#include <cuda_fp16.h>
#include <math.h>
#include <stdint.h>

#define SEQ     2048
#define HIDDEN  1024
#define NH      16
#define HD      64
#define NL      8
#define VOCABSZ 50272
#define FFN     4096
#define EPSV    1e-5f

#define OFF_WQKV 0ULL
#define OFF_WO   25165824ULL
#define OFF_W1   33554432ULL
#define OFF_W2   67108864ULL
#define OFF_LM   100663296ULL
#define W_TOTAL  152141824ULL

// ---------------- scratch ----------------
__device__ float g_x  [(size_t)SEQ * HIDDEN];
__device__ float g_qkv[(size_t)SEQ * 3 * HIDDEN];
__device__ float g_cos[(size_t)SEQ * (HD / 2)];
__device__ float g_sin[(size_t)SEQ * (HD / 2)];
__device__ __half g_wh[W_TOTAL];
__device__ __half g_sh[(size_t)SEQ * 3 * HIDDEN];
__device__ __half g_hh[(size_t)SEQ * HIDDEN];
__device__ __half g_ah[(size_t)SEQ * HIDDEN];
__device__ __half g_mh[(size_t)SEQ * FFN];

// ---------------- helpers ----------------
__device__ __forceinline__ uint32_t smem_u32(const void* p) {
    uint32_t a;
    asm("{ .reg .u64 t; cvta.to.shared.u64 t, %1; cvt.u32.u64 %0, t; }" : "=r"(a) : "l"(p));
    return a;
}
__device__ __forceinline__ float warpSum(float v) {
    #pragma unroll
    for (int o = 16; o; o >>= 1) v += __shfl_xor_sync(0xffffffffu, v, o);
    return v;
}
__device__ __forceinline__ float blockReduceSum(float v, float* red) {
    int lane = threadIdx.x & 31, w = threadIdx.x >> 5;
    v = warpSum(v);
    if (lane == 0) red[w] = v;
    __syncthreads();
    if (w == 0) {
        float r = (lane < (int)(blockDim.x >> 5)) ? red[lane] : 0.0f;
        r = warpSum(r);
        if (lane == 0) red[0] = r;
    }
    __syncthreads();
    float out = red[0];
    __syncthreads();
    return out;
}
__device__ __forceinline__ void mma_f16(float* c, const uint32_t* a, const uint32_t* b) {
    asm volatile(
        "mma.sync.aligned.m16n8k16.row.col.f32.f16.f16.f32 "
        "{%0,%1,%2,%3}, {%4,%5,%6,%7}, {%8,%9}, {%0,%1,%2,%3};"
        : "+f"(c[0]), "+f"(c[1]), "+f"(c[2]), "+f"(c[3])
        : "r"(a[0]), "r"(a[1]), "r"(a[2]), "r"(a[3]), "r"(b[0]), "r"(b[1]));
}
__device__ __forceinline__ void ldmx4(uint32_t* d, uint32_t addr) {
    asm volatile("ldmatrix.sync.aligned.m8n8.x4.shared.b16 {%0,%1,%2,%3}, [%4];"
                 : "=r"(d[0]), "=r"(d[1]), "=r"(d[2]), "=r"(d[3]) : "r"(addr));
}
__device__ __forceinline__ void ldmx4t(uint32_t* d, uint32_t addr) {
    asm volatile("ldmatrix.sync.aligned.m8n8.x4.trans.shared.b16 {%0,%1,%2,%3}, [%4];"
                 : "=r"(d[0]), "=r"(d[1]), "=r"(d[2]), "=r"(d[3]) : "r"(addr));
}
__device__ __forceinline__ void cpa16(uint32_t s, const void* g, int srcsz) {
    asm volatile("cp.async.cg.shared.global [%0], [%1], 16, %2;"
                 :: "r"(s), "l"(g), "r"(srcsz) : "memory");
}
__device__ __forceinline__ void cpa_commit() {
    asm volatile("cp.async.commit_group;" ::: "memory");
}
__device__ __forceinline__ void cpa_wait0() {
    asm volatile("cp.async.wait_group 0;" ::: "memory");
}

// ---------------- fused weight prep: all five tensors -> contiguous fp16 planes ----------------
#define N4_QKV 6291456ULL
#define N4_WO  2097152ULL
#define N4_W1  8388608ULL
#define N4_W2  8388608ULL
#define N4_LM  12869632ULL
#define N4_ALL (N4_QKV + N4_WO + N4_W1 + N4_W2 + N4_LM)   // 38035456

__global__ void wprep_all_kernel(const float4* __restrict__ wqkv, const float4* __restrict__ wo,
                                 const float4* __restrict__ w1,  const float4* __restrict__ w2,
                                 const float4* __restrict__ lm,  uint32_t* __restrict__ d) {
    size_t i = (size_t)blockIdx.x * blockDim.x + threadIdx.x;
    if (i >= N4_ALL) return;
    const float4* src;
    size_t lo;
    if (i < N4_QKV)                            { src = wqkv; lo = i; }
    else if (i < N4_QKV + N4_WO)               { src = wo;   lo = i - N4_QKV; }
    else if (i < N4_QKV + N4_WO + N4_W1)       { src = w1;   lo = i - N4_QKV - N4_WO; }
    else if (i < N4_QKV + N4_WO + N4_W1 + N4_W2) { src = w2; lo = i - N4_QKV - N4_WO - N4_W1; }
    else                                       { src = lm;   lo = i - N4_QKV - N4_WO - N4_W1 - N4_W2; }
    float4 f = src[lo];
    __half2 h0 = __floats2half2_rn(f.x, f.y);
    __half2 h1 = __floats2half2_rn(f.z, f.w);
    d[2 * i] = *(uint32_t*)&h0;
    d[2 * i + 1] = *(uint32_t*)&h1;
}

// ---------------- embedding + rmsnorm ----------------
__global__ void embed_rmsnorm_kernel(const int* __restrict__ ids,
                                     const float* __restrict__ wte,
                                     float* __restrict__ out) {
    __shared__ float red[32];
    int t = blockIdx.x;
    const float* row = wte + (size_t)ids[t] * HIDDEN;
    float v[4]; float ss = 0.0f;
    #pragma unroll
    for (int i = 0; i < 4; i++) { v[i] = row[threadIdx.x + i * 256]; ss += v[i] * v[i]; }
    ss = blockReduceSum(ss, red);
    float sc = rsqrtf(ss * (1.0f / HIDDEN) + EPSV);
    #pragma unroll
    for (int i = 0; i < 4; i++)
        out[(size_t)t * HIDDEN + threadIdx.x + i * 256] = v[i] * sc;
}

// ---------------- rmsnorm: fp32 in -> fp16 plane ----------------
__global__ void rmsnorm_f16_kernel(const float* __restrict__ in,
                                   __half* __restrict__ oh) {
    __shared__ float red[32];
    int t = blockIdx.x;
    const float* row = in + (size_t)t * HIDDEN;
    float v[4]; float ss = 0.0f;
    #pragma unroll
    for (int i = 0; i < 4; i++) {
        int idx = 2 * threadIdx.x + (i & 1) + (i >> 1) * 512;
        v[i] = row[idx];
        ss += v[i] * v[i];
    }
    ss = blockReduceSum(ss, red);
    float sc = rsqrtf(ss * (1.0f / HIDDEN) + EPSV);
    #pragma unroll
    for (int p = 0; p < 2; p++) {
        __half2 hh = __floats2half2_rn(v[2 * p] * sc, v[2 * p + 1] * sc);
        size_t off = (size_t)t * HIDDEN + 2 * threadIdx.x + p * 512;
        *(uint32_t*)((char*)oh + off * 2) = *(uint32_t*)&hh;
    }
}

// ---------------- rope tables ----------------
__global__ void rope_init_kernel(float* __restrict__ ctab, float* __restrict__ stab) {
    int t = blockIdx.x, i = threadIdx.x;
    float invf = (float)pow(10000.0, -(double)(2 * i) / (double)HD);
    float ang = (float)t * invf;
    float s, c;
    sincosf(ang, &s, &c);
    ctab[t * 32 + i] = c;
    stab[t * 32 + i] = s;
}

// ---------------- per-token: q,k rmsnorm+rope -> fp16; v -> fp16 ----------------
__global__ void qknorm_rope_kernel(const float* __restrict__ qkv,
                                   const float* __restrict__ ctab,
                                   const float* __restrict__ stab,
                                   __half* __restrict__ oh) {
    int t = blockIdx.x, tid = threadIdx.x, lane = tid & 31, wid = tid >> 5;
    float cc = ctab[t * 32 + lane], ssn = stab[t * 32 + lane];
    #pragma unroll
    for (int task = wid; task < 32; task += 8) {
        int h = task & 15, wv = task >> 4;
        size_t base = (size_t)t * (3 * HIDDEN) + (size_t)wv * HIDDEN + h * HD;
        float2 x = *(const float2*)(qkv + base + 2 * lane);
        float ss = warpSum(x.x * x.x + x.y * x.y);
        float sc = rsqrtf(ss * (1.0f / HD) + EPSV);
        float x0 = x.x * sc, x1 = x.y * sc;
        float y0 = x1 * cc - x0 * ssn;
        float y1 = x1 * ssn + x0 * cc;
        __half2 hh = __floats2half2_rn(y0, y1);
        *(uint32_t*)((char*)oh + (base + 2 * lane) * 2) = *(uint32_t*)&hh;
    }
    size_t vb = (size_t)t * (3 * HIDDEN) + 2 * HIDDEN;
    float4 v = *(const float4*)(qkv + vb + tid * 4);
    __half2 h0 = __floats2half2_rn(v.x, v.y);
    __half2 h1 = __floats2half2_rn(v.z, v.w);
    *(uint2*)((char*)oh + (vb + tid * 4) * 2) = make_uint2(*(uint32_t*)&h0, *(uint32_t*)&h1);
}

// ================= fused flash attention (pure fp16, cp.async pipelined) =================
#define FRS       72
#define FT_BYTES  (64 * FRS * 2)              // 9216
#define KV_STAGE  (2 * FT_BYTES)
#define FLASH_SMEM (FT_BYTES + 2 * KV_STAGE)  // 46080

__global__ void __launch_bounds__(128, 2)
flash_attn_kernel(const __half* __restrict__ qkv_g, __half* __restrict__ outh) {
    extern __shared__ char fsm[];
    uint32_t sb = smem_u32(fsm);
    uint32_t uQ = sb;

    int tid = threadIdx.x, lane = tid & 31, wid = tid >> 5;
    int h = blockIdx.y;
    int qt = (int)gridDim.x - 1 - (int)blockIdx.x;
    int bm = qt * 64;

    int r = tid >> 1, c0 = (tid & 1) * 32;
    uint32_t soff = (uint32_t)(r * (FRS * 2) + c0 * 2);

    {
        const char* gQ = (const char*)(qkv_g + (size_t)(bm + r) * (3 * HIDDEN) + h * HD + c0);
        #pragma unroll
        for (int g = 0; g < 4; g++)
            cpa16(uQ + soff + g * 16, gQ + g * 16, 16);
        const char* gK = (const char*)(qkv_g + (size_t)r * (3 * HIDDEN) + HIDDEN + h * HD + c0);
        uint32_t st = sb + FT_BYTES;
        #pragma unroll
        for (int g = 0; g < 4; g++) {
            cpa16(st + soff + g * 16,            gK + g * 16, 16);
            cpa16(st + FT_BYTES + soff + g * 16, gK + HIDDEN * 2 + g * 16, 16);
        }
        cpa_commit();
    }

    uint32_t qh[4][4];
    float o[8][4] = {};
    float m[2] = {-INFINITY, -INFINITY};
    float l[2] = {0.0f, 0.0f};

    for (int jt = 0; jt <= qt; jt++) {
        cpa_wait0();
        __syncthreads();

        if (jt == 0) {
            uint32_t qoff = (uint32_t)(((wid * 16 + (lane & 15)) * FRS + ((lane >> 4) & 1) * 8) * 2);
            #pragma unroll
            for (int ks = 0; ks < 4; ks++)
                ldmx4(qh[ks], uQ + qoff + ks * 32);
        }
        if (jt + 1 <= qt) {
            const char* gK = (const char*)(qkv_g + (size_t)((jt + 1) * 64 + r) * (3 * HIDDEN) + HIDDEN + h * HD + c0);
            uint32_t st = sb + FT_BYTES + (uint32_t)((jt + 1) & 1) * KV_STAGE;
            #pragma unroll
            for (int g = 0; g < 4; g++) {
                cpa16(st + soff + g * 16,            gK + g * 16, 16);
                cpa16(st + FT_BYTES + soff + g * 16, gK + HIDDEN * 2 + g * 16, 16);
            }
            cpa_commit();
        }

        uint32_t stg = sb + FT_BYTES + (uint32_t)(jt & 1) * KV_STAGE;
        uint32_t uK = stg, uV = stg + FT_BYTES;

        float s[8][4] = {};
        uint32_t bbase = (uint32_t)(((((lane >> 4) & 1) * 8 + (lane & 7)) * FRS
                                     + ((lane >> 3) & 1) * 8) * 2);
        #pragma unroll
        for (int ks = 0; ks < 4; ks++) {
            #pragma unroll
            for (int nb = 0; nb < 4; nb++) {
                uint32_t kk[4];
                uint32_t bo = bbase + (uint32_t)(nb * 16 * FRS * 2) + (uint32_t)(ks * 32);
                ldmx4(kk, uK + bo);
                mma_f16(s[nb * 2],     qh[ks], kk + 0);
                mma_f16(s[nb * 2 + 1], qh[ks], kk + 2);
            }
        }
        #pragma unroll
        for (int nt = 0; nt < 8; nt++)
            #pragma unroll
            for (int c = 0; c < 4; c++) s[nt][c] *= 0.125f;

        if (jt == qt) {
            int q0 = wid * 16 + (lane >> 2);
            int q1 = q0 + 8;
            #pragma unroll
            for (int nt = 0; nt < 8; nt++) {
                int j0 = nt * 8 + (lane & 3) * 2;
                if (j0     > q0) s[nt][0] = -INFINITY;
                if (j0 + 1 > q0) s[nt][1] = -INFINITY;
                if (j0     > q1) s[nt][2] = -INFINITY;
                if (j0 + 1 > q1) s[nt][3] = -INFINITY;
            }
        }

        #pragma unroll
        for (int hh = 0; hh < 2; hh++) {
            float rm = -INFINITY;
            #pragma unroll
            for (int nt = 0; nt < 8; nt++)
                rm = fmaxf(rm, fmaxf(s[nt][2 * hh], s[nt][2 * hh + 1]));
            rm = fmaxf(rm, __shfl_xor_sync(0xffffffffu, rm, 1));
            rm = fmaxf(rm, __shfl_xor_sync(0xffffffffu, rm, 2));
            float mnew = fmaxf(m[hh], rm);
            float corr = __expf(m[hh] - mnew);
            float rs = 0.0f;
            #pragma unroll
            for (int nt = 0; nt < 8; nt++) {
                float p0 = __expf(s[nt][2 * hh]     - mnew);
                float p1 = __expf(s[nt][2 * hh + 1] - mnew);
                s[nt][2 * hh] = p0; s[nt][2 * hh + 1] = p1;
                rs += p0 + p1;
            }
            rs += __shfl_xor_sync(0xffffffffu, rs, 1);
            rs += __shfl_xor_sync(0xffffffffu, rs, 2);
            l[hh] = l[hh] * corr + rs;
            m[hh] = mnew;
            #pragma unroll
            for (int dt = 0; dt < 8; dt++) {
                o[dt][2 * hh] *= corr; o[dt][2 * hh + 1] *= corr;
            }
        }

        #pragma unroll
        for (int jks = 0; jks < 4; jks++) {
            float* ce = s[2 * jks];
            float* co = s[2 * jks + 1];
            uint32_t pa[4];
            {
                __half2 h0 = __floats2half2_rn(ce[0], ce[1]);
                __half2 h1 = __floats2half2_rn(ce[2], ce[3]);
                __half2 h2 = __floats2half2_rn(co[0], co[1]);
                __half2 h3 = __floats2half2_rn(co[2], co[3]);
                pa[0] = *(uint32_t*)&h0; pa[1] = *(uint32_t*)&h1;
                pa[2] = *(uint32_t*)&h2; pa[3] = *(uint32_t*)&h3;
            }
            uint32_t vbase = (uint32_t)(((jks * 16 + (lane & 15)) * FRS
                                         + ((lane >> 4) & 1) * 8) * 2);
            #pragma unroll
            for (int db = 0; db < 4; db++) {
                uint32_t vv[4];
                ldmx4t(vv, uV + vbase + (uint32_t)(db * 32));
                mma_f16(o[db * 2],     pa, vv + 0);
                mma_f16(o[db * 2 + 1], pa, vv + 2);
            }
        }
    }

    float inv0 = 1.0f / l[0], inv1 = 1.0f / l[1];
    int row0 = bm + wid * 16 + (lane >> 2);
    #pragma unroll
    for (int dt = 0; dt < 8; dt++) {
        int col = h * HD + dt * 8 + (lane & 3) * 2;
        __half2 hh0 = __floats2half2_rn(o[dt][0] * inv0, o[dt][1] * inv0);
        __half2 hh1 = __floats2half2_rn(o[dt][2] * inv1, o[dt][3] * inv1);
        *(uint32_t*)((char*)outh + ((size_t)row0 * HIDDEN + col) * 2) = *(uint32_t*)&hh0;
        *(uint32_t*)((char*)outh + ((size_t)(row0 + 8) * HIDDEN + col) * 2) = *(uint32_t*)&hh1;
    }
}

// ================= fp16 1-pass GEMM, KC=64, row stride 72 =================
// EPI 0: C = v (fp32)   EPI 1: C = R + v (fp32)   EPI 2: Oh = f16(relu(v)^2)
#define GRS 72

template <int EPI, int BM>
__global__ void __launch_bounds__(256, 2)
gemm_f16_kernel(const __half* __restrict__ Ah, const __half* __restrict__ Bh,
                float* __restrict__ C, const float* __restrict__ R,
                __half* __restrict__ Oh,
                int M, int N, int K) {
    constexpr int MT = (BM == 128) ? 4 : 2;
    constexpr int ABY = BM * GRS * 2;     // 18432 / 9216
    constexpr int BBY = 128 * GRS * 2;    // 18432
    constexpr int STG = ABY + BBY;

    extern __shared__ char gsm[];
    int tid = threadIdx.x, lane = tid & 31, wid = tid >> 5;
    int wm = wid >> 2, wn = wid & 3;
    int bm = blockIdx.y * BM, bn = blockIdx.x * 128;

    uint32_t sb = smem_u32(gsm);

    // A loader: covers BM rows x 128B per chunk
    int arow; uint32_t so_a; const char* gAh; int aRounds, aStride;
    if (BM == 128) {
        arow = tid >> 1; int half = tid & 1;
        so_a = (uint32_t)(arow * (GRS * 2) + half * 16);
        gAh = (const char*)(Ah + (size_t)(bm + arow) * K + half * 8);
        aRounds = 4; aStride = 32;
    } else {
        arow = tid >> 2; int seg = tid & 3;
        so_a = (uint32_t)(arow * (GRS * 2) + seg * 16);
        gAh = (const char*)(Ah + (size_t)(bm + arow) * K + seg * 8);
        aRounds = 2; aStride = 64;
    }
    // B loader: 128 rows x 128B per chunk
    int brow = tid >> 1, bhalf = tid & 1;
    int bgrow = bn + brow;
    bool bok = bgrow < N;
    int browc = bok ? bgrow : (N - 1);
    uint32_t so_b = (uint32_t)(brow * (GRS * 2) + bhalf * 16);
    const char* gBh = (const char*)(Bh + (size_t)browc * K + bhalf * 8);
    int bsz = bok ? 16 : 0;

    uint32_t aoff = (uint32_t)(((wm * (MT * 16) + (lane & 15)) * GRS + ((lane >> 4) & 1) * 8) * 2);
    uint32_t boff = (uint32_t)(((wn * 32 + ((lane >> 4) & 1) * 8 + (lane & 7)) * GRS
                                + ((lane >> 3) & 1) * 8) * 2);

    float acc[MT][4][4] = {};
    int nCh = K >> 6;

    {
        uint32_t s0 = sb;
        #pragma unroll
        for (int g = 0; g < 4; g++)
            if (g < aRounds) cpa16(s0 + so_a + g * (uint32_t)aStride, gAh + g * aStride, 16);
        #pragma unroll
        for (int g = 0; g < 4; g++)
            cpa16(s0 + ABY + so_b + g * 32, gBh + g * 32, bsz);
        cpa_commit();
    }

    for (int s = 0; s < nCh; s++) {
        cpa_wait0();
        __syncthreads();

        if (s + 1 < nCh) {
            uint32_t s1 = sb + (uint32_t)((s + 1) & 1) * STG;
            int kb = (s + 1) * 128;   // 64 fp16 = 128 bytes
            #pragma unroll
            for (int g = 0; g < 4; g++)
                if (g < aRounds) cpa16(s1 + so_a + g * (uint32_t)aStride, gAh + kb + g * aStride, 16);
            #pragma unroll
            for (int g = 0; g < 4; g++)
                cpa16(s1 + ABY + so_b + g * 32, gBh + kb + g * 32, bsz);
            cpa_commit();
        }

        uint32_t st = sb + (uint32_t)(s & 1) * STG;
        uint32_t uAh = st, uB = st + ABY;
        #pragma unroll
        for (int ks = 0; ks < 4; ks++) {
            uint32_t k2 = (uint32_t)(ks * 32);
            uint32_t aH[MT][4], bH[2][4];
            #pragma unroll
            for (int mt = 0; mt < MT; mt++) ldmx4(aH[mt], uAh + aoff + mt * (16 * GRS * 2) + k2);
            #pragma unroll
            for (int np = 0; np < 2; np++) ldmx4(bH[np], uB + boff + np * (16 * GRS * 2) + k2);
            #pragma unroll
            for (int mt = 0; mt < MT; mt++)
                #pragma unroll
                for (int nt = 0; nt < 4; nt++)
                    mma_f16(acc[mt][nt], aH[mt], &bH[nt >> 1][(nt & 1) * 2]);
        }
    }

    #pragma unroll
    for (int mt = 0; mt < MT; mt++) {
        int rw = bm + wm * (MT * 16) + mt * 16 + (lane >> 2);
        #pragma unroll
        for (int nt = 0; nt < 4; nt++) {
            int col = bn + wn * 32 + nt * 8 + (lane & 3) * 2;
            if (col < N) {
                float* c = acc[mt][nt];
                float v0 = c[0], v1 = c[1], v2 = c[2], v3 = c[3];
                if (EPI == 1) {
                    float2 r0 = *(const float2*)(R + (size_t)rw * N + col);
                    float2 r1 = *(const float2*)(R + (size_t)(rw + 8) * N + col);
                    v0 += r0.x; v1 += r0.y; v2 += r1.x; v3 += r1.y;
                }
                if (EPI == 2) {
                    v0 = fmaxf(v0, 0.f); v0 *= v0;
                    v1 = fmaxf(v1, 0.f); v1 *= v1;
                    v2 = fmaxf(v2, 0.f); v2 *= v2;
                    v3 = fmaxf(v3, 0.f); v3 *= v3;
                    __half2 hh0 = __floats2half2_rn(v0, v1);
                    __half2 hh1 = __floats2half2_rn(v2, v3);
                    *(uint32_t*)((char*)Oh + ((size_t)rw * N + col) * 2) = *(uint32_t*)&hh0;
                    *(uint32_t*)((char*)Oh + ((size_t)(rw + 8) * N + col) * 2) = *(uint32_t*)&hh1;
                } else {
                    *(float2*)(C + (size_t)rw * N + col) = make_float2(v0, v1);
                    *(float2*)(C + (size_t)(rw + 8) * N + col) = make_float2(v2, v3);
                }
            }
        }
    }
}

#define GS_128 (2 * (128 * GRS * 2 + 128 * GRS * 2))   // 73728
#define GS_64  (2 * (64 * GRS * 2 + 128 * GRS * 2))    // 55296

// ---------------- host launcher ----------------
extern "C" void kernel_launch(void* const* d_in, const int* in_sizes, int n_in,
                              void* d_out, int out_size) {
    const int*   ids  = (const int*)d_in[0];
    const float* wte  = (const float*)d_in[1];
    const float* wqkv = (const float*)d_in[2];
    const float* wo   = (const float*)d_in[3];
    const float* w1   = (const float*)d_in[4];
    const float* w2   = (const float*)d_in[5];
    const float* lm   = (const float*)d_in[6];
    float* out = (float*)d_out;

    float *px, *pqkv, *pcos, *psin;
    __half *pwh, *psh, *phh, *pah, *pmh;
    cudaGetSymbolAddress((void**)&px,   g_x);
    cudaGetSymbolAddress((void**)&pqkv, g_qkv);
    cudaGetSymbolAddress((void**)&pcos, g_cos);
    cudaGetSymbolAddress((void**)&psin, g_sin);
    cudaGetSymbolAddress((void**)&pwh,  g_wh);
    cudaGetSymbolAddress((void**)&psh,  g_sh);
    cudaGetSymbolAddress((void**)&phh,  g_hh);
    cudaGetSymbolAddress((void**)&pah,  g_ah);
    cudaGetSymbolAddress((void**)&pmh,  g_mh);

    cudaFuncSetAttribute(flash_attn_kernel,
                         cudaFuncAttributeMaxDynamicSharedMemorySize, FLASH_SMEM);
    cudaFuncSetAttribute(gemm_f16_kernel<0, 128>,
                         cudaFuncAttributeMaxDynamicSharedMemorySize, GS_128);
    cudaFuncSetAttribute(gemm_f16_kernel<2, 128>,
                         cudaFuncAttributeMaxDynamicSharedMemorySize, GS_128);
    cudaFuncSetAttribute(gemm_f16_kernel<1, 64>,
                         cudaFuncAttributeMaxDynamicSharedMemorySize, GS_64);

    // ---- weight prep (single fused launch; dst planes contiguous in input order) ----
    wprep_all_kernel<<<(unsigned)((N4_ALL + 255) / 256), 256>>>(
        (const float4*)wqkv, (const float4*)wo, (const float4*)w1,
        (const float4*)w2, (const float4*)lm, (uint32_t*)pwh);

    rope_init_kernel<<<SEQ, 32>>>(pcos, psin);
    embed_rmsnorm_kernel<<<SEQ, 256>>>(ids, wte, px);

    for (int l = 0; l < NL; l++) {
        __half* wqkv_h = pwh + OFF_WQKV + (size_t)l * 3145728;
        __half* wo_h   = pwh + OFF_WO + (size_t)l * 1048576;
        __half* w1_h   = pwh + OFF_W1 + (size_t)l * 4194304;
        __half* w2_h   = pwh + OFF_W2 + (size_t)l * 4194304;

        rmsnorm_f16_kernel<<<SEQ, 256>>>(px, phh);
        gemm_f16_kernel<0, 128><<<dim3(24, 16), 256, GS_128>>>(
            phh, wqkv_h, pqkv, nullptr, nullptr, SEQ, 3 * HIDDEN, HIDDEN);
        qknorm_rope_kernel<<<SEQ, 256>>>(pqkv, pcos, psin, psh);
        flash_attn_kernel<<<dim3(SEQ / 64, NH), 128, FLASH_SMEM>>>(psh, pah);
        gemm_f16_kernel<1, 64><<<dim3(8, 32), 256, GS_64>>>(
            pah, wo_h, px, px, nullptr, SEQ, HIDDEN, HIDDEN);

        rmsnorm_f16_kernel<<<SEQ, 256>>>(px, phh);
        gemm_f16_kernel<2, 128><<<dim3(32, 16), 256, GS_128>>>(
            phh, w1_h, nullptr, nullptr, pmh, SEQ, FFN, HIDDEN);
        gemm_f16_kernel<1, 64><<<dim3(8, 32), 256, GS_64>>>(
            pmh, w2_h, px, px, nullptr, SEQ, HIDDEN, FFN);
    }

    rmsnorm_f16_kernel<<<SEQ, 256>>>(px, phh);
    gemm_f16_kernel<0, 128><<<dim3((VOCABSZ + 127) / 128, 16), 256, GS_128>>>(
        phh, pwh + OFF_LM, out, nullptr, nullptr, SEQ, VOCABSZ, HIDDEN);
}

// round 17
// speedup vs baseline: 1.0798x; 1.0798x over previous
#include <cuda_runtime.h>
#include <cuda_bf16.h>
#include <cuda_fp16.h>
#include <math.h>
#include <stdint.h>

#define SEQ     2048
#define HIDDEN  1024
#define NH      16
#define HD      64
#define NL      8
#define VOCABSZ 50272
#define FFN     4096
#define EPSV    1e-5f

#define OFF_WQKV 0ULL
#define OFF_WO   25165824ULL
#define OFF_W1   33554432ULL
#define OFF_W2   67108864ULL
#define OFF_LM   100663296ULL
#define W_TOTAL  152141824ULL

// ---------------- scratch ----------------
__device__ float g_x  [(size_t)SEQ * HIDDEN];
__device__ float g_qkv[(size_t)SEQ * 3 * HIDDEN];
__device__ float g_cos[(size_t)SEQ * (HD / 2)];
__device__ float g_sin[(size_t)SEQ * (HD / 2)];
__device__ __half g_wh[W_TOTAL];
__device__ __half g_sh[(size_t)SEQ * 3 * HIDDEN];
__device__ __half g_hh[(size_t)SEQ * HIDDEN];
__device__ __half g_ah[(size_t)SEQ * HIDDEN];
__device__ __half g_mh[(size_t)SEQ * FFN];

// ---------------- helpers ----------------
__device__ __forceinline__ uint32_t smem_u32(const void* p) {
    uint32_t a;
    asm("{ .reg .u64 t; cvta.to.shared.u64 t, %1; cvt.u32.u64 %0, t; }" : "=r"(a) : "l"(p));
    return a;
}
__device__ __forceinline__ float warpSum(float v) {
    #pragma unroll
    for (int o = 16; o; o >>= 1) v += __shfl_xor_sync(0xffffffffu, v, o);
    return v;
}
__device__ __forceinline__ float blockReduceSum(float v, float* red) {
    int lane = threadIdx.x & 31, w = threadIdx.x >> 5;
    v = warpSum(v);
    if (lane == 0) red[w] = v;
    __syncthreads();
    if (w == 0) {
        float r = (lane < (int)(blockDim.x >> 5)) ? red[lane] : 0.0f;
        r = warpSum(r);
        if (lane == 0) red[0] = r;
    }
    __syncthreads();
    float out = red[0];
    __syncthreads();
    return out;
}
__device__ __forceinline__ void mma_f16(float* c, const uint32_t* a, const uint32_t* b) {
    asm volatile(
        "mma.sync.aligned.m16n8k16.row.col.f32.f16.f16.f32 "
        "{%0,%1,%2,%3}, {%4,%5,%6,%7}, {%8,%9}, {%0,%1,%2,%3};"
        : "+f"(c[0]), "+f"(c[1]), "+f"(c[2]), "+f"(c[3])
        : "r"(a[0]), "r"(a[1]), "r"(a[2]), "r"(a[3]), "r"(b[0]), "r"(b[1]));
}
__device__ __forceinline__ void ldmx4(uint32_t* d, uint32_t addr) {
    asm volatile("ldmatrix.sync.aligned.m8n8.x4.shared.b16 {%0,%1,%2,%3}, [%4];"
                 : "=r"(d[0]), "=r"(d[1]), "=r"(d[2]), "=r"(d[3]) : "r"(addr));
}
__device__ __forceinline__ void ldmx4t(uint32_t* d, uint32_t addr) {
    asm volatile("ldmatrix.sync.aligned.m8n8.x4.trans.shared.b16 {%0,%1,%2,%3}, [%4];"
                 : "=r"(d[0]), "=r"(d[1]), "=r"(d[2]), "=r"(d[3]) : "r"(addr));
}
__device__ __forceinline__ void cpa16(uint32_t s, const void* g, int srcsz) {
    asm volatile("cp.async.cg.shared.global [%0], [%1], 16, %2;"
                 :: "r"(s), "l"(g), "r"(srcsz) : "memory");
}
__device__ __forceinline__ void cpa_commit() {
    asm volatile("cp.async.commit_group;" ::: "memory");
}
__device__ __forceinline__ void cpa_wait0() {
    asm volatile("cp.async.wait_group 0;" ::: "memory");
}

// ---------------- fused weight prep: all five tensors -> contiguous fp16 planes ----------------
#define N4_QKV 6291456ULL
#define N4_WO  2097152ULL
#define N4_W1  8388608ULL
#define N4_W2  8388608ULL
#define N4_LM  12869632ULL
#define N4_ALL (N4_QKV + N4_WO + N4_W1 + N4_W2 + N4_LM)

__global__ void wprep_all_kernel(const float4* __restrict__ wqkv, const float4* __restrict__ wo,
                                 const float4* __restrict__ w1,  const float4* __restrict__ w2,
                                 const float4* __restrict__ lm,  uint32_t* __restrict__ d) {
    size_t i = (size_t)blockIdx.x * blockDim.x + threadIdx.x;
    if (i >= N4_ALL) return;
    const float4* src;
    size_t lo;
    if (i < N4_QKV)                              { src = wqkv; lo = i; }
    else if (i < N4_QKV + N4_WO)                 { src = wo;   lo = i - N4_QKV; }
    else if (i < N4_QKV + N4_WO + N4_W1)         { src = w1;   lo = i - N4_QKV - N4_WO; }
    else if (i < N4_QKV + N4_WO + N4_W1 + N4_W2) { src = w2;   lo = i - N4_QKV - N4_WO - N4_W1; }
    else                                         { src = lm;   lo = i - N4_QKV - N4_WO - N4_W1 - N4_W2; }
    float4 f = src[lo];
    __half2 h0 = __floats2half2_rn(f.x, f.y);
    __half2 h1 = __floats2half2_rn(f.z, f.w);
    d[2 * i] = *(uint32_t*)&h0;
    d[2 * i + 1] = *(uint32_t*)&h1;
}

// ---------------- embedding + rmsnorm ----------------
__global__ void embed_rmsnorm_kernel(const int* __restrict__ ids,
                                     const float* __restrict__ wte,
                                     float* __restrict__ out) {
    __shared__ float red[32];
    int t = blockIdx.x;
    const float* row = wte + (size_t)ids[t] * HIDDEN;
    float v[4]; float ss = 0.0f;
    #pragma unroll
    for (int i = 0; i < 4; i++) { v[i] = row[threadIdx.x + i * 256]; ss += v[i] * v[i]; }
    ss = blockReduceSum(ss, red);
    float sc = rsqrtf(ss * (1.0f / HIDDEN) + EPSV);
    #pragma unroll
    for (int i = 0; i < 4; i++)
        out[(size_t)t * HIDDEN + threadIdx.x + i * 256] = v[i] * sc;
}

// ---------------- rmsnorm: fp32 in -> fp16 plane ----------------
__global__ void rmsnorm_f16_kernel(const float* __restrict__ in,
                                   __half* __restrict__ oh) {
    __shared__ float red[32];
    int t = blockIdx.x;
    const float* row = in + (size_t)t * HIDDEN;
    float v[4]; float ss = 0.0f;
    #pragma unroll
    for (int i = 0; i < 4; i++) {
        int idx = 2 * threadIdx.x + (i & 1) + (i >> 1) * 512;
        v[i] = row[idx];
        ss += v[i] * v[i];
    }
    ss = blockReduceSum(ss, red);
    float sc = rsqrtf(ss * (1.0f / HIDDEN) + EPSV);
    #pragma unroll
    for (int p = 0; p < 2; p++) {
        __half2 hh = __floats2half2_rn(v[2 * p] * sc, v[2 * p + 1] * sc);
        size_t off = (size_t)t * HIDDEN + 2 * threadIdx.x + p * 512;
        *(uint32_t*)((char*)oh + off * 2) = *(uint32_t*)&hh;
    }
}

// ---------------- rope tables ----------------
__global__ void rope_init_kernel(float* __restrict__ ctab, float* __restrict__ stab) {
    int t = blockIdx.x, i = threadIdx.x;
    float invf = (float)pow(10000.0, -(double)(2 * i) / (double)HD);
    float ang = (float)t * invf;
    float s, c;
    sincosf(ang, &s, &c);
    ctab[t * 32 + i] = c;
    stab[t * 32 + i] = s;
}

// ---------------- per-token: q,k rmsnorm+rope -> fp16; v -> fp16 ----------------
__global__ void qknorm_rope_kernel(const float* __restrict__ qkv,
                                   const float* __restrict__ ctab,
                                   const float* __restrict__ stab,
                                   __half* __restrict__ oh) {
    int t = blockIdx.x, tid = threadIdx.x, lane = tid & 31, wid = tid >> 5;
    float cc = ctab[t * 32 + lane], ssn = stab[t * 32 + lane];
    #pragma unroll
    for (int task = wid; task < 32; task += 8) {
        int h = task & 15, wv = task >> 4;
        size_t base = (size_t)t * (3 * HIDDEN) + (size_t)wv * HIDDEN + h * HD;
        float2 x = *(const float2*)(qkv + base + 2 * lane);
        float ss = warpSum(x.x * x.x + x.y * x.y);
        float sc = rsqrtf(ss * (1.0f / HD) + EPSV);
        float x0 = x.x * sc, x1 = x.y * sc;
        float y0 = x1 * cc - x0 * ssn;
        float y1 = x1 * ssn + x0 * cc;
        __half2 hh = __floats2half2_rn(y0, y1);
        *(uint32_t*)((char*)oh + (base + 2 * lane) * 2) = *(uint32_t*)&hh;
    }
    size_t vb = (size_t)t * (3 * HIDDEN) + 2 * HIDDEN;
    float4 v = *(const float4*)(qkv + vb + tid * 4);
    __half2 h0 = __floats2half2_rn(v.x, v.y);
    __half2 h1 = __floats2half2_rn(v.z, v.w);
    *(uint2*)((char*)oh + (vb + tid * 4) * 2) = make_uint2(*(uint32_t*)&h0, *(uint32_t*)&h1);
}

// ================= fused flash attention (pure fp16, cp.async pipelined) =================
#define FRS       72
#define FT_BYTES  (64 * FRS * 2)
#define KV_STAGE  (2 * FT_BYTES)
#define FLASH_SMEM (FT_BYTES + 2 * KV_STAGE)

__global__ void __launch_bounds__(128, 2)
flash_attn_kernel(const __half* __restrict__ qkv_g, __half* __restrict__ outh) {
    extern __shared__ char fsm[];
    uint32_t sb = smem_u32(fsm);
    uint32_t uQ = sb;

    int tid = threadIdx.x, lane = tid & 31, wid = tid >> 5;
    int h = blockIdx.y;
    int qt = (int)gridDim.x - 1 - (int)blockIdx.x;
    int bm = qt * 64;

    int r = tid >> 1, c0 = (tid & 1) * 32;
    uint32_t soff = (uint32_t)(r * (FRS * 2) + c0 * 2);

    {
        const char* gQ = (const char*)(qkv_g + (size_t)(bm + r) * (3 * HIDDEN) + h * HD + c0);
        #pragma unroll
        for (int g = 0; g < 4; g++)
            cpa16(uQ + soff + g * 16, gQ + g * 16, 16);
        const char* gK = (const char*)(qkv_g + (size_t)r * (3 * HIDDEN) + HIDDEN + h * HD + c0);
        uint32_t st = sb + FT_BYTES;
        #pragma unroll
        for (int g = 0; g < 4; g++) {
            cpa16(st + soff + g * 16,            gK + g * 16, 16);
            cpa16(st + FT_BYTES + soff + g * 16, gK + HIDDEN * 2 + g * 16, 16);
        }
        cpa_commit();
    }

    uint32_t qh[4][4];
    float o[8][4] = {};
    float m[2] = {-INFINITY, -INFINITY};
    float l[2] = {0.0f, 0.0f};

    for (int jt = 0; jt <= qt; jt++) {
        cpa_wait0();
        __syncthreads();

        if (jt == 0) {
            uint32_t qoff = (uint32_t)(((wid * 16 + (lane & 15)) * FRS + ((lane >> 4) & 1) * 8) * 2);
            #pragma unroll
            for (int ks = 0; ks < 4; ks++)
                ldmx4(qh[ks], uQ + qoff + ks * 32);
        }
        if (jt + 1 <= qt) {
            const char* gK = (const char*)(qkv_g + (size_t)((jt + 1) * 64 + r) * (3 * HIDDEN) + HIDDEN + h * HD + c0);
            uint32_t st = sb + FT_BYTES + (uint32_t)((jt + 1) & 1) * KV_STAGE;
            #pragma unroll
            for (int g = 0; g < 4; g++) {
                cpa16(st + soff + g * 16,            gK + g * 16, 16);
                cpa16(st + FT_BYTES + soff + g * 16, gK + HIDDEN * 2 + g * 16, 16);
            }
            cpa_commit();
        }

        uint32_t stg = sb + FT_BYTES + (uint32_t)(jt & 1) * KV_STAGE;
        uint32_t uK = stg, uV = stg + FT_BYTES;

        float s[8][4] = {};
        uint32_t bbase = (uint32_t)(((((lane >> 4) & 1) * 8 + (lane & 7)) * FRS
                                     + ((lane >> 3) & 1) * 8) * 2);
        #pragma unroll
        for (int ks = 0; ks < 4; ks++) {
            #pragma unroll
            for (int nb = 0; nb < 4; nb++) {
                uint32_t kk[4];
                uint32_t bo = bbase + (uint32_t)(nb * 16 * FRS * 2) + (uint32_t)(ks * 32);
                ldmx4(kk, uK + bo);
                mma_f16(s[nb * 2],     qh[ks], kk + 0);
                mma_f16(s[nb * 2 + 1], qh[ks], kk + 2);
            }
        }
        #pragma unroll
        for (int nt = 0; nt < 8; nt++)
            #pragma unroll
            for (int c = 0; c < 4; c++) s[nt][c] *= 0.125f;

        if (jt == qt) {
            int q0 = wid * 16 + (lane >> 2);
            int q1 = q0 + 8;
            #pragma unroll
            for (int nt = 0; nt < 8; nt++) {
                int j0 = nt * 8 + (lane & 3) * 2;
                if (j0     > q0) s[nt][0] = -INFINITY;
                if (j0 + 1 > q0) s[nt][1] = -INFINITY;
                if (j0     > q1) s[nt][2] = -INFINITY;
                if (j0 + 1 > q1) s[nt][3] = -INFINITY;
            }
        }

        #pragma unroll
        for (int hh = 0; hh < 2; hh++) {
            float rm = -INFINITY;
            #pragma unroll
            for (int nt = 0; nt < 8; nt++)
                rm = fmaxf(rm, fmaxf(s[nt][2 * hh], s[nt][2 * hh + 1]));
            rm = fmaxf(rm, __shfl_xor_sync(0xffffffffu, rm, 1));
            rm = fmaxf(rm, __shfl_xor_sync(0xffffffffu, rm, 2));
            float mnew = fmaxf(m[hh], rm);
            float corr = __expf(m[hh] - mnew);
            float rs = 0.0f;
            #pragma unroll
            for (int nt = 0; nt < 8; nt++) {
                float p0 = __expf(s[nt][2 * hh]     - mnew);
                float p1 = __expf(s[nt][2 * hh + 1] - mnew);
                s[nt][2 * hh] = p0; s[nt][2 * hh + 1] = p1;
                rs += p0 + p1;
            }
            rs += __shfl_xor_sync(0xffffffffu, rs, 1);
            rs += __shfl_xor_sync(0xffffffffu, rs, 2);
            l[hh] = l[hh] * corr + rs;
            m[hh] = mnew;
            #pragma unroll
            for (int dt = 0; dt < 8; dt++) {
                o[dt][2 * hh] *= corr; o[dt][2 * hh + 1] *= corr;
            }
        }

        #pragma unroll
        for (int jks = 0; jks < 4; jks++) {
            float* ce = s[2 * jks];
            float* co = s[2 * jks + 1];
            uint32_t pa[4];
            {
                __half2 h0 = __floats2half2_rn(ce[0], ce[1]);
                __half2 h1 = __floats2half2_rn(ce[2], ce[3]);
                __half2 h2 = __floats2half2_rn(co[0], co[1]);
                __half2 h3 = __floats2half2_rn(co[2], co[3]);
                pa[0] = *(uint32_t*)&h0; pa[1] = *(uint32_t*)&h1;
                pa[2] = *(uint32_t*)&h2; pa[3] = *(uint32_t*)&h3;
            }
            uint32_t vbase = (uint32_t)(((jks * 16 + (lane & 15)) * FRS
                                         + ((lane >> 4) & 1) * 8) * 2);
            #pragma unroll
            for (int db = 0; db < 4; db++) {
                uint32_t vv[4];
                ldmx4t(vv, uV + vbase + (uint32_t)(db * 32));
                mma_f16(o[db * 2],     pa, vv + 0);
                mma_f16(o[db * 2 + 1], pa, vv + 2);
            }
        }
    }

    float inv0 = 1.0f / l[0], inv1 = 1.0f / l[1];
    int row0 = bm + wid * 16 + (lane >> 2);
    #pragma unroll
    for (int dt = 0; dt < 8; dt++) {
        int col = h * HD + dt * 8 + (lane & 3) * 2;
        __half2 hh0 = __floats2half2_rn(o[dt][0] * inv0, o[dt][1] * inv0);
        __half2 hh1 = __floats2half2_rn(o[dt][2] * inv1, o[dt][3] * inv1);
        *(uint32_t*)((char*)outh + ((size_t)row0 * HIDDEN + col) * 2) = *(uint32_t*)&hh0;
        *(uint32_t*)((char*)outh + ((size_t)(row0 + 8) * HIDDEN + col) * 2) = *(uint32_t*)&hh1;
    }
}

// ================= fp16 1-pass GEMM (R15 shape: KC=32, RS=40) =================
// EPI 0: C = v (fp32)   EPI 1: C = R + v (fp32)   EPI 2: Oh = f16(relu(v)^2)
// SWAP=1: blockIdx.x -> M tile, blockIdx.y -> N tile (B-tile reuse across consecutive CTAs)
#define RS 40

template <int EPI, int BM, int SWAP>
__global__ void __launch_bounds__(256, 2)
gemm_f16_kernel(const __half* __restrict__ Ah, const __half* __restrict__ Bh,
                float* __restrict__ C, const float* __restrict__ R,
                __half* __restrict__ Oh,
                int M, int N, int K) {
    constexpr int MT = (BM == 128) ? 4 : 2;
    constexpr int ABY = BM * RS * 2;
    constexpr int BBY = 128 * RS * 2;
    constexpr int STG = ABY + BBY;

    extern __shared__ char gsm[];
    int tid = threadIdx.x, lane = tid & 31, wid = tid >> 5;
    int wm = wid >> 2, wn = wid & 3;
    int bm = (SWAP ? blockIdx.x : blockIdx.y) * BM;
    int bn = (SWAP ? blockIdx.y : blockIdx.x) * 128;

    uint32_t sb = smem_u32(gsm);

    int arow, acpa_n; uint32_t so_a; const char* gAh;
    if (BM == 128) {
        arow = tid >> 1; int half = tid & 1; acpa_n = 2;
        so_a = (uint32_t)(arow * 80 + half * 32);
        gAh = (const char*)(Ah + (size_t)(bm + arow) * K + half * 16);
    } else {
        arow = tid >> 2; int seg = tid & 3; acpa_n = 1;
        so_a = (uint32_t)(arow * 80 + seg * 16);
        gAh = (const char*)(Ah + (size_t)(bm + arow) * K + seg * 8);
    }
    int brow = tid >> 1, bhalf = tid & 1;
    int bgrow = bn + brow;
    bool bok = bgrow < N;
    int browc = bok ? bgrow : (N - 1);
    uint32_t so_b = (uint32_t)(brow * 80 + bhalf * 32);
    const char* gBh = (const char*)(Bh + (size_t)browc * K + bhalf * 16);
    int bsz = bok ? 16 : 0;

    uint32_t aoff = (uint32_t)(((wm * (MT * 16) + (lane & 15)) * RS + ((lane >> 4) & 1) * 8) * 2);
    uint32_t boff = (uint32_t)(((wn * 32 + ((lane >> 4) & 1) * 8 + (lane & 7)) * RS
                                + ((lane >> 3) & 1) * 8) * 2);

    float acc[MT][4][4] = {};
    int nCh = K >> 5;

    {
        uint32_t s0 = sb;
        #pragma unroll
        for (int g = 0; g < 2; g++)
            if (g < acpa_n) cpa16(s0 + so_a + g * 16, gAh + g * 16, 16);
        cpa16(s0 + ABY + so_b,      gBh, bsz);
        cpa16(s0 + ABY + so_b + 16, gBh + 16, bsz);
        cpa_commit();
    }

    for (int s = 0; s < nCh; s++) {
        cpa_wait0();
        __syncthreads();

        if (s + 1 < nCh) {
            uint32_t s1 = sb + (uint32_t)((s + 1) & 1) * STG;
            int kb = (s + 1) * 64;
            #pragma unroll
            for (int g = 0; g < 2; g++)
                if (g < acpa_n) cpa16(s1 + so_a + g * 16, gAh + kb + g * 16, 16);
            cpa16(s1 + ABY + so_b,      gBh + kb, bsz);
            cpa16(s1 + ABY + so_b + 16, gBh + kb + 16, bsz);
            cpa_commit();
        }

        uint32_t st = sb + (uint32_t)(s & 1) * STG;
        uint32_t uAh = st, uB = st + ABY;
        #pragma unroll
        for (int ks = 0; ks < 2; ks++) {
            uint32_t k2 = (uint32_t)(ks * 32);
            uint32_t aH[MT][4], bH[2][4];
            #pragma unroll
            for (int mt = 0; mt < MT; mt++) ldmx4(aH[mt], uAh + aoff + mt * (16 * RS * 2) + k2);
            #pragma unroll
            for (int np = 0; np < 2; np++) ldmx4(bH[np], uB + boff + np * (16 * RS * 2) + k2);
            #pragma unroll
            for (int mt = 0; mt < MT; mt++)
                #pragma unroll
                for (int nt = 0; nt < 4; nt++)
                    mma_f16(acc[mt][nt], aH[mt], &bH[nt >> 1][(nt & 1) * 2]);
        }
    }

    #pragma unroll
    for (int mt = 0; mt < MT; mt++) {
        int rw = bm + wm * (MT * 16) + mt * 16 + (lane >> 2);
        #pragma unroll
        for (int nt = 0; nt < 4; nt++) {
            int col = bn + wn * 32 + nt * 8 + (lane & 3) * 2;
            if (col < N) {
                float* c = acc[mt][nt];
                float v0 = c[0], v1 = c[1], v2 = c[2], v3 = c[3];
                if (EPI == 1) {
                    float2 r0 = *(const float2*)(R + (size_t)rw * N + col);
                    float2 r1 = *(const float2*)(R + (size_t)(rw + 8) * N + col);
                    v0 += r0.x; v1 += r0.y; v2 += r1.x; v3 += r1.y;
                }
                if (EPI == 2) {
                    v0 = fmaxf(v0, 0.f); v0 *= v0;
                    v1 = fmaxf(v1, 0.f); v1 *= v1;
                    v2 = fmaxf(v2, 0.f); v2 *= v2;
                    v3 = fmaxf(v3, 0.f); v3 *= v3;
                    __half2 hh0 = __floats2half2_rn(v0, v1);
                    __half2 hh1 = __floats2half2_rn(v2, v3);
                    *(uint32_t*)((char*)Oh + ((size_t)rw * N + col) * 2) = *(uint32_t*)&hh0;
                    *(uint32_t*)((char*)Oh + ((size_t)(rw + 8) * N + col) * 2) = *(uint32_t*)&hh1;
                } else {
                    *(float2*)(C + (size_t)rw * N + col) = make_float2(v0, v1);
                    *(float2*)(C + (size_t)(rw + 8) * N + col) = make_float2(v2, v3);
                }
            }
        }
    }
}

#define GS_128 (2 * (128 * RS * 2 + 128 * RS * 2))   // 40960
#define GS_64  (2 * (64 * RS * 2 + 128 * RS * 2))    // 30720

// ---------------- host launcher ----------------
extern "C" void kernel_launch(void* const* d_in, const int* in_sizes, int n_in,
                              void* d_out, int out_size) {
    const int*   ids  = (const int*)d_in[0];
    const float* wte  = (const float*)d_in[1];
    const float* wqkv = (const float*)d_in[2];
    const float* wo   = (const float*)d_in[3];
    const float* w1   = (const float*)d_in[4];
    const float* w2   = (const float*)d_in[5];
    const float* lm   = (const float*)d_in[6];
    float* out = (float*)d_out;

    float *px, *pqkv, *pcos, *psin;
    __half *pwh, *psh, *phh, *pah, *pmh;
    cudaGetSymbolAddress((void**)&px,   g_x);
    cudaGetSymbolAddress((void**)&pqkv, g_qkv);
    cudaGetSymbolAddress((void**)&pcos, g_cos);
    cudaGetSymbolAddress((void**)&psin, g_sin);
    cudaGetSymbolAddress((void**)&pwh,  g_wh);
    cudaGetSymbolAddress((void**)&psh,  g_sh);
    cudaGetSymbolAddress((void**)&phh,  g_hh);
    cudaGetSymbolAddress((void**)&pah,  g_ah);
    cudaGetSymbolAddress((void**)&pmh,  g_mh);

    cudaFuncSetAttribute(flash_attn_kernel,
                         cudaFuncAttributeMaxDynamicSharedMemorySize, FLASH_SMEM);
    cudaFuncSetAttribute(gemm_f16_kernel<0, 128, 0>,
                         cudaFuncAttributeMaxDynamicSharedMemorySize, GS_128);
    cudaFuncSetAttribute(gemm_f16_kernel<0, 128, 1>,
                         cudaFuncAttributeMaxDynamicSharedMemorySize, GS_128);
    cudaFuncSetAttribute(gemm_f16_kernel<2, 128, 0>,
                         cudaFuncAttributeMaxDynamicSharedMemorySize, GS_128);
    cudaFuncSetAttribute(gemm_f16_kernel<1, 64, 0>,
                         cudaFuncAttributeMaxDynamicSharedMemorySize, GS_64);

    // ---- weight prep (single fused launch) ----
    wprep_all_kernel<<<(unsigned)((N4_ALL + 255) / 256), 256>>>(
        (const float4*)wqkv, (const float4*)wo, (const float4*)w1,
        (const float4*)w2, (const float4*)lm, (uint32_t*)pwh);

    rope_init_kernel<<<SEQ, 32>>>(pcos, psin);
    embed_rmsnorm_kernel<<<SEQ, 256>>>(ids, wte, px);

    for (int l = 0; l < NL; l++) {
        __half* wqkv_h = pwh + OFF_WQKV + (size_t)l * 3145728;
        __half* wo_h   = pwh + OFF_WO + (size_t)l * 1048576;
        __half* w1_h   = pwh + OFF_W1 + (size_t)l * 4194304;
        __half* w2_h   = pwh + OFF_W2 + (size_t)l * 4194304;

        rmsnorm_f16_kernel<<<SEQ, 256>>>(px, phh);
        gemm_f16_kernel<0, 128, 0><<<dim3(24, 16), 256, GS_128>>>(
            phh, wqkv_h, pqkv, nullptr, nullptr, SEQ, 3 * HIDDEN, HIDDEN);
        qknorm_rope_kernel<<<SEQ, 256>>>(pqkv, pcos, psin, psh);
        flash_attn_kernel<<<dim3(SEQ / 64, NH), 128, FLASH_SMEM>>>(psh, pah);
        gemm_f16_kernel<1, 64, 0><<<dim3(8, 32), 256, GS_64>>>(
            pah, wo_h, px, px, nullptr, SEQ, HIDDEN, HIDDEN);

        rmsnorm_f16_kernel<<<SEQ, 256>>>(px, phh);
        gemm_f16_kernel<2, 128, 0><<<dim3(32, 16), 256, GS_128>>>(
            phh, w1_h, nullptr, nullptr, pmh, SEQ, FFN, HIDDEN);
        gemm_f16_kernel<1, 64, 0><<<dim3(8, 32), 256, GS_64>>>(
            pmh, w2_h, px, px, nullptr, SEQ, HIDDEN, FFN);
    }

    rmsnorm_f16_kernel<<<SEQ, 256>>>(px, phh);
    // lm head: SWAP grid so consecutive CTAs share a B (weight) tile
    gemm_f16_kernel<0, 128, 1><<<dim3(16, (VOCABSZ + 127) / 128), 256, GS_128>>>(
        phh, pwh + OFF_LM, out, nullptr, nullptr, SEQ, VOCABSZ, HIDDEN);
}